// round 4
// baseline (speedup 1.0000x reference)
#include <cuda_runtime.h>
#include <cuda_bf16.h>

// SoftHistogram via fine-histogram factorization:
//   out[ch][j] = normalize_j( (1/P) * sum_t counts[ch][t] * W[t][j] )
// W[t][j] = per-pixel-normalized Gaussian weight at fine-bin center (t+0.5)/TF.
// Quantization to TF=4096 levels is a second-order (curvature) bias; measured
// rel_err 1.8e-5 at the 1e-3 threshold.
//
// R3 changes vs R2 (66.3us):
//  - init: one warp per t-row (2 expf/lane + shfl reduce) -> full-chip MUFU
//  - hist: global RED.ADD (1.29 cyc/lane spread) replaces shared ATOMS
//    (2 cyc/lane) + removes smem zero/merge epilogue

#define TF    4096              // fine histogram bins
#define NCH   24                // 8 * 3 channels
#define BINS  64
#define PPC   (512 * 512)       // pixels per channel
#define HBLK  32                // hist blocks per channel

__device__ unsigned int g_counts[NCH][TF];   // per-channel fine histogram
__device__ float        g_W[TF][BINS];       // normalized weight table

// ---------------------------------------------------------------------------
// Kernel A: blocks 0..95 zero g_counts (24576 uint4, 256/block).
// Blocks 96..607: weight table, one warp per t-row. Each lane computes bins
// {lane, lane+32}, warp-reduces the row sum, writes the normalized pair.
// ---------------------------------------------------------------------------
__global__ void __launch_bounds__(256) hx_init(const float* __restrict__ centers) {
    const int b   = blockIdx.x;
    const int tid = threadIdx.x;
    if (b < 96) {
        reinterpret_cast<uint4*>(g_counts)[b * 256 + tid] = make_uint4(0u, 0u, 0u, 0u);
        return;
    }
    const int warp = tid >> 5;
    const int lane = tid & 31;
    const int t    = (b - 96) * 8 + warp;            // 0..4095
    const float x  = (t + 0.5f) * (1.0f / TF);
    const float invs = 1.0f / (0.02f + 1e-12f);      // matches reference SIGMA guard

    float z0 = (x - __ldg(&centers[lane]))      * invs;
    float z1 = (x - __ldg(&centers[lane + 32])) * invs;
    float e0 = expf(-0.5f * z0 * z0);
    float e1 = expf(-0.5f * z1 * z1);

    float s = e0 + e1;
#pragma unroll
    for (int off = 16; off > 0; off >>= 1)
        s += __shfl_xor_sync(0xffffffffu, s, off);
    const float r = 1.0f / (s + 1e-12f);

    g_W[t][lane]      = e0 * r;
    g_W[t][lane + 32] = e1 * r;
}

// ---------------------------------------------------------------------------
// Kernel B: fine histogram, straight to global RED.ADD (no smem).
// Grid (HBLK, 24), 256 threads, 32 pixels/thread via float4.
// x*4096 is an exact pow2 multiply; unsigned min clamps x==1.0 (and any
// negative, which would wrap to huge) into bin TF-1.
// ---------------------------------------------------------------------------
__global__ void __launch_bounds__(256) hx_hist(const float* __restrict__ x) {
    const int tid = threadIdx.x;
    const int ch  = blockIdx.y;
    const int blk = blockIdx.x;                       // 0..HBLK-1
    const float4* __restrict__ p =
        reinterpret_cast<const float4*>(x + (size_t)ch * PPC
                                          + (size_t)blk * (PPC / HBLK));
    unsigned int* __restrict__ gc = g_counts[ch];

#pragma unroll 4
    for (int i = 0; i < PPC / HBLK / (256 * 4); i++) {
        float4 v = p[i * 256 + tid];
        unsigned t0 = min((unsigned)__float2int_rz(v.x * (float)TF), (unsigned)(TF - 1));
        unsigned t1 = min((unsigned)__float2int_rz(v.y * (float)TF), (unsigned)(TF - 1));
        unsigned t2 = min((unsigned)__float2int_rz(v.z * (float)TF), (unsigned)(TF - 1));
        unsigned t3 = min((unsigned)__float2int_rz(v.w * (float)TF), (unsigned)(TF - 1));
        atomicAdd(&gc[t0], 1u);    // result unused -> RED.E.ADD
        atomicAdd(&gc[t1], 1u);
        atomicAdd(&gc[t2], 1u);
        atomicAdd(&gc[t3], 1u);
    }
}

// ---------------------------------------------------------------------------
// Kernel C: per-channel contraction hist[j] = sum_t cnt[t] * W[t][j], then the
// two reference normalizations. One block per channel.
// ---------------------------------------------------------------------------
__global__ void __launch_bounds__(256) hx_final(float* __restrict__ out) {
    const int ch  = blockIdx.x;
    const int tid = threadIdx.x;

    float acc[BINS];
#pragma unroll
    for (int j = 0; j < BINS; j++) acc[j] = 0.0f;

    for (int t = tid; t < TF; t += 256) {
        float c = (float)g_counts[ch][t];
        const float4* __restrict__ w = reinterpret_cast<const float4*>(g_W[t]);
#pragma unroll
        for (int q = 0; q < 16; q++) {
            float4 ww = w[q];
            acc[4 * q + 0] += c * ww.x;
            acc[4 * q + 1] += c * ww.y;
            acc[4 * q + 2] += c * ww.z;
            acc[4 * q + 3] += c * ww.w;
        }
    }

#pragma unroll
    for (int off = 16; off > 0; off >>= 1) {
#pragma unroll
        for (int j = 0; j < BINS; j++)
            acc[j] += __shfl_down_sync(0xffffffffu, acc[j], off);
    }

    __shared__ float hist[BINS];
    __shared__ float ssum;
    if (tid < BINS) hist[tid] = 0.0f;
    __syncthreads();

    if ((tid & 31) == 0) {                 // one leader per warp (8 warps)
#pragma unroll
        for (int j = 0; j < BINS; j++)
            atomicAdd(&hist[j], acc[j]);
    }
    __syncthreads();

    if (tid == 0) {
        float s = 0.0f;
        for (int j = 0; j < BINS; j++) s += hist[j];
        ssum = s * (1.0f / (float)PPC);
    }
    __syncthreads();

    if (tid < BINS) {
        float m = hist[tid] * (1.0f / (float)PPC);   // mean over pixels
        out[ch * BINS + tid] = m / (ssum + 1e-12f);  // per-image normalize
    }
}

// ---------------------------------------------------------------------------
extern "C" void kernel_launch(void* const* d_in, const int* in_sizes, int n_in,
                              void* d_out, int out_size) {
    const float* x       = (const float*)d_in[0];   // (8,3,512,512) fp32
    const float* centers = (const float*)d_in[1];   // (64,) fp32
    float* out           = (float*)d_out;           // (8,3,64) fp32

    hx_init<<<96 + TF / 8, 256>>>(centers);
    hx_hist<<<dim3(HBLK, 24), 256>>>(x);
    hx_final<<<24, 256>>>(out);
}

// round 6
// speedup vs baseline: 3.3914x; 3.3914x over previous
#include <cuda_runtime.h>
#include <cuda_bf16.h>

// SoftHistogram via fine-histogram factorization:
//   out[ch][j] = normalize( sum_t counts[ch][t] * W[t][j] )
// W[t][j] = per-pixel-normalized Gaussian weight at x_t = t/TF (round-binning:
// bin = round(x*TF) via the 2^23 magic-FMA trick, rows t = 0..TF inclusive).
//
// R4 vs R2 (66.3us best): shared-ATOMS hist (R3 global-RED regressed), fast
// warp-per-row init, TF 4096->2048, FFMA+LOP3 binning, split contraction +
// separate tiny normalize.

#define TF    2048
#define ROWS  (TF + 1)            // 2049 table rows (bin 0..2048)
#define RPAD  2052                // row pad, multiple of 4 for uint4 zeroing
#define NCH   24                  // 8 * 3 channels
#define BINS  64
#define PPC   (512 * 512)         // pixels per channel
#define HBLK  16                  // hist blocks per channel
#define PXB   (PPC / HBLK)        // 16384 pixels per hist block
#define ZBLK  52                  // zeroing blocks in init
#define TBLK  ((ROWS + 7) / 8)    // 257 table blocks (8 rows/block)

__device__ unsigned int g_counts[NCH][RPAD];  // per-channel fine histogram
__device__ float        g_W[ROWS][BINS];      // normalized weight table
__device__ float        g_hist[NCH][BINS];    // contraction accumulators

// ---------------------------------------------------------------------------
// Kernel A: blocks [0,ZBLK) zero g_counts (+ block 0 zeroes g_hist).
// Blocks [ZBLK, ZBLK+TBLK): weight table, one warp per t-row; each lane does
// bins {lane, lane+32}, warp-reduces the row sum, writes normalized pair.
// ---------------------------------------------------------------------------
__global__ void __launch_bounds__(256) hx_init(const float* __restrict__ centers) {
    const int b   = blockIdx.x;
    const int tid = threadIdx.x;
    if (b < ZBLK) {
        for (int i = b * 256 + tid; i < NCH * RPAD / 4; i += ZBLK * 256)
            reinterpret_cast<uint4*>(g_counts)[i] = make_uint4(0u, 0u, 0u, 0u);
        if (b == 0 && tid < NCH * BINS / 4)
            reinterpret_cast<float4*>(g_hist)[tid] = make_float4(0.f, 0.f, 0.f, 0.f);
        return;
    }
    const int warp = tid >> 5;
    const int lane = tid & 31;
    const int t    = (b - ZBLK) * 8 + warp;
    if (t >= ROWS) return;
    const float x    = (float)t * (1.0f / (float)TF);
    const float invs = 1.0f / (0.02f + 1e-12f);      // reference SIGMA guard

    float z0 = (x - __ldg(&centers[lane]))      * invs;
    float z1 = (x - __ldg(&centers[lane + 32])) * invs;
    float e0 = expf(-0.5f * z0 * z0);
    float e1 = expf(-0.5f * z1 * z1);

    float s = e0 + e1;
#pragma unroll
    for (int off = 16; off > 0; off >>= 1)
        s += __shfl_xor_sync(0xffffffffu, s, off);
    const float r = 1.0f / (s + 1e-12f);

    g_W[t][lane]      = e0 * r;
    g_W[t][lane + 32] = e1 * r;
}

// ---------------------------------------------------------------------------
// Kernel B: shared-memory fine histogram. Grid (HBLK, 24), 256 threads,
// 64 pixels/thread via float4. bin = round(x*TF) from the low mantissa bits
// of fma(x, TF, 2^23): exact for x in [0,1] (x*TF is a pow2 scale; the single
// RN happens on the +2^23 add). Mask 0xFFF keeps bins 0..2048 in range.
// ---------------------------------------------------------------------------
__global__ void __launch_bounds__(256) hx_hist(const float* __restrict__ x) {
    __shared__ unsigned int sh[RPAD];
    const int tid = threadIdx.x;

    for (int i = tid; i < RPAD; i += 256) sh[i] = 0u;
    __syncthreads();

    const int ch  = blockIdx.y;
    const int blk = blockIdx.x;
    const float4* __restrict__ p =
        reinterpret_cast<const float4*>(x + (size_t)ch * PPC + (size_t)blk * PXB);

    const float MAGIC = 8388608.0f;   // 2^23

#pragma unroll 4
    for (int i = 0; i < PXB / (256 * 4); i++) {
        float4 v = p[i * 256 + tid];
        unsigned b0 = __float_as_uint(fmaf(v.x, (float)TF, MAGIC)) & 0xFFFu;
        unsigned b1 = __float_as_uint(fmaf(v.y, (float)TF, MAGIC)) & 0xFFFu;
        unsigned b2 = __float_as_uint(fmaf(v.z, (float)TF, MAGIC)) & 0xFFFu;
        unsigned b3 = __float_as_uint(fmaf(v.w, (float)TF, MAGIC)) & 0xFFFu;
        atomicAdd(&sh[b0], 1u);
        atomicAdd(&sh[b1], 1u);
        atomicAdd(&sh[b2], 1u);
        atomicAdd(&sh[b3], 1u);
    }
    __syncthreads();

    unsigned int* __restrict__ gc = g_counts[ch];
    for (int i = tid; i < ROWS; i += 256) {
        unsigned v = sh[i];
        if (v) atomicAdd(&gc[i], v);
    }
}

// ---------------------------------------------------------------------------
// Kernel C: contraction split across grid (8, 24). Block (split, ch) handles
// rows [split*257, min(+257, ROWS)); warp shfl-tree reduce; lane0 REDs the 64
// partial sums into g_hist[ch].
// ---------------------------------------------------------------------------
__global__ void __launch_bounds__(256) hx_contract() {
    const int split = blockIdx.x;
    const int ch    = blockIdx.y;
    const int tid   = threadIdx.x;

    float acc[BINS];
#pragma unroll
    for (int j = 0; j < BINS; j++) acc[j] = 0.0f;

    const int r0 = split * 257;
    const int r1 = min(r0 + 257, ROWS);
    for (int r = r0 + tid; r < r1; r += 256) {
        float c = (float)g_counts[ch][r];
        if (c != 0.0f) {
            const float4* __restrict__ w = reinterpret_cast<const float4*>(g_W[r]);
#pragma unroll
            for (int q = 0; q < 16; q++) {
                float4 ww = w[q];
                acc[4 * q + 0] += c * ww.x;
                acc[4 * q + 1] += c * ww.y;
                acc[4 * q + 2] += c * ww.z;
                acc[4 * q + 3] += c * ww.w;
            }
        }
    }

#pragma unroll
    for (int off = 16; off > 0; off >>= 1) {
#pragma unroll
        for (int j = 0; j < BINS; j++)
            acc[j] += __shfl_down_sync(0xffffffffu, acc[j], off);
    }

    if ((tid & 31) == 0) {
#pragma unroll
        for (int j = 0; j < BINS; j++)
            atomicAdd(&g_hist[ch][j], acc[j]);   // RED.F32 to 1536 hot words
    }
}

// ---------------------------------------------------------------------------
// Kernel D: normalize, matching the reference FP structure:
//   m = hist_sum/P ; out = m / (sum_j m + 1e-12)
// ---------------------------------------------------------------------------
__global__ void hx_norm(float* __restrict__ out) {
    const int ch  = blockIdx.x;
    const int tid = threadIdx.x;          // 64 threads

    float m = g_hist[ch][tid] * (1.0f / (float)PPC);
    float s = m;
#pragma unroll
    for (int off = 16; off > 0; off >>= 1)
        s += __shfl_xor_sync(0xffffffffu, s, off);

    __shared__ float ws[2];
    if ((tid & 31) == 0) ws[tid >> 5] = s;
    __syncthreads();
    float tot = ws[0] + ws[1];

    out[ch * BINS + tid] = m / (tot + 1e-12f);
}

// ---------------------------------------------------------------------------
extern "C" void kernel_launch(void* const* d_in, const int* in_sizes, int n_in,
                              void* d_out, int out_size) {
    const float* x       = (const float*)d_in[0];   // (8,3,512,512) fp32
    const float* centers = (const float*)d_in[1];   // (64,) fp32
    float* out           = (float*)d_out;           // (8,3,64) fp32

    hx_init<<<ZBLK + TBLK, 256>>>(centers);
    hx_hist<<<dim3(HBLK, NCH), 256>>>(x);
    hx_contract<<<dim3(8, NCH), 256>>>();
    hx_norm<<<NCH, BINS>>>(out);
}